// round 5
// baseline (speedup 1.0000x reference)
#include <cuda_runtime.h>
#include <cstdint>

#define NS 32
#define NV 8
#define N_NODES 16384
#define N_EDGES 131072
#define NEF 128
#define HID 128
#define WN 1600
#define DD 56
#define INV_SQRT3 0.57735026918962576451f
#define PATH_NORM 0.15811388300841897f /* 1/sqrt(40) */
#define EPS 1e-5f

// Scratch (static device globals — allowed; no runtime allocation)
__device__ float g_h[(size_t)N_EDGES * HID];     // 64 MB: relu(ea@W1+b1)
__device__ float g_sums[(size_t)N_NODES * DD];   // segment sums
__device__ float g_cnt[N_NODES];                 // segment counts
__device__ float g_pre[(size_t)N_NODES * DD];    // pre-BN node features
__device__ float g_stats[72];                    // [0:32) sum_s, [32:64) sum_s2, [64:72) sum_v2
__device__ int   g_idx32;                        // 1 if edge_index is int32, 0 if int64

// ---- packed f32x2 helpers (FFMA2: 2 MACs/instr, restores full FP32 rate) ----
#define PACKDUP(dst, s) do { unsigned _u = __float_as_uint(s); \
    asm("mov.b64 %0, {%1, %1};" : "=l"(dst) : "r"(_u)); } while (0)
#define FMA2(d, a, b) asm("fma.rn.f32x2 %0, %1, %2, %0;" : "+l"(d) : "l"(a), "l"(b))
#define ADD2(d, a, b) asm("add.rn.f32x2 %0, %1, %2;" : "=l"(d) : "l"(a), "l"(b))
#define UNPACK2(lo, hi, v) do { unsigned _lo, _hi; \
    asm("mov.b64 {%0, %1}, %2;" : "=r"(_lo), "=r"(_hi) : "l"(v)); \
    lo = __uint_as_float(_lo); hi = __uint_as_float(_hi); } while (0)

typedef unsigned long long u64;

// ============================================================
// K0: zero accumulators + detect edge_index dtype
// ============================================================
__global__ void k0_zero(const long long* __restrict__ eidx) {
    int idx = blockIdx.x * 256 + threadIdx.x;
    if (idx < N_NODES * DD) g_sums[idx] = 0.f;
    if (idx < N_NODES)      g_cnt[idx]  = 0.f;
    if (idx < 72)           g_stats[idx] = 0.f;
    if (blockIdx.x == 0 && threadIdx.x == 0) {
        // Genuine int64 indices all lie in [0, N_NODES). int32 pairs read as
        // int64 are >= 2^32 with prob ~1-1/16384 per word.
        int is32 = 0;
        for (int i = 0; i < 64; ++i) {
            long long v = eidx[i];
            if (v < 0 || v >= N_NODES) { is32 = 1; break; }
        }
        g_idx32 = is32;
    }
}

// ============================================================
// K1: h = relu(edge_attr @ W1 + b1)   [131072 x 128] -> g_h
// 128x128 tile per block, 256 threads, f32x2-packed SGEMM.
// ============================================================
__global__ __launch_bounds__(256, 1)
void k1_gemm_relu(const float* __restrict__ ea, const float* __restrict__ W1,
                  const float* __restrict__ b1) {
    extern __shared__ float sm[];
    float* As = sm;          // [e][k] 128x128
    float* Bs = sm + 16384;  // [k][n] 128x128
    int tid = threadIdx.x;
    int e0 = blockIdx.x * 128;

    for (int it = 0; it < 16; ++it) {
        int idx = tid + it * 256;        // 4096 float4 units
        int r = idx >> 5, c4 = idx & 31;
        float4 v = *(const float4*)&ea[(size_t)(e0 + r) * NEF + c4 * 4];
        *(float4*)&As[r * 128 + c4 * 4] = v;
        float4 w = *(const float4*)&W1[(size_t)r * HID + c4 * 4];
        *(float4*)&Bs[r * 128 + c4 * 4] = w;
    }
    __syncthreads();

    int tx = tid & 15, ty = tid >> 4;
    u64 acc[8][4];
    #pragma unroll
    for (int i = 0; i < 8; ++i)
        #pragma unroll
        for (int j = 0; j < 4; ++j) acc[i][j] = 0ull;

    #pragma unroll 2
    for (int k4 = 0; k4 < 32; ++k4) {
        int k0 = k4 * 4;
        float4 av[8];
        #pragma unroll
        for (int mi = 0; mi < 8; ++mi) {
            int m = (mi < 4) ? (ty * 4 + mi) : (64 + ty * 4 + mi - 4);
            av[mi] = *(const float4*)&As[m * 128 + k0];
        }
        #pragma unroll
        for (int kk = 0; kk < 4; ++kk) {
            int k = k0 + kk;
            ulonglong2 bl = *(const ulonglong2*)&Bs[k * 128 + tx * 4];
            ulonglong2 bh = *(const ulonglong2*)&Bs[k * 128 + 64 + tx * 4];
            u64 bb0 = bl.x, bb1 = bl.y, bb2 = bh.x, bb3 = bh.y;
            #pragma unroll
            for (int mi = 0; mi < 8; ++mi) {
                float a_s = ((const float*)&av[mi])[kk];
                u64 aa; PACKDUP(aa, a_s);
                FMA2(acc[mi][0], aa, bb0);
                FMA2(acc[mi][1], aa, bb1);
                FMA2(acc[mi][2], aa, bb2);
                FMA2(acc[mi][3], aa, bb3);
            }
        }
    }

    #pragma unroll
    for (int mi = 0; mi < 8; ++mi) {
        int m = (mi < 4) ? (ty * 4 + mi) : (64 + ty * 4 + mi - 4);
        #pragma unroll
        for (int p = 0; p < 4; ++p) {
            int n = (p < 2) ? (tx * 4 + p * 2) : (64 + tx * 4 + (p - 2) * 2);
            float lo, hi; UNPACK2(lo, hi, acc[mi][p]);
            lo = fmaxf(lo + __ldg(&b1[n]), 0.f);
            hi = fmaxf(hi + __ldg(&b1[n + 1]), 0.f);
            *(float2*)&g_h[(size_t)(e0 + m) * HID + n] = make_float2(lo, hi);
        }
    }
}

// ============================================================
// K2: fused  w = h@W2 + b2  -> tensor product -> atomic scatter
// ============================================================
__global__ __launch_bounds__(256, 1)
void k2_fused(const float* __restrict__ node_attr,
              const float* __restrict__ edge_sh,
              const float* __restrict__ W2,
              const float* __restrict__ b2,
              const long long* __restrict__ eidx) {
    extern __shared__ float sm[];
    float* As  = sm;              // [e][k] 16384 (h tile)
    float* Bs  = sm + 16384;      // [k][n] 16384 (reused as Cs[e][c])
    float* b2s = sm + 32768;      // 128
    float* sxs = sm + 32896;      // [e][32] xs*ss
    float* xsh = sm + 36992;      // [e][32] xs
    float* dvv = sm + 41088;      // [e][8]  dot(xv,sv)/sqrt3
    float* xvs = sm + 42112;      // [e][24] xv*ss
    float* svs = sm + 45184;      // [e][3]
    int*   esrc = (int*)(sm + 45568); // [128]

    int tid = threadIdx.x;
    int e0 = blockIdx.x * 128;

    // ---- per-edge prep (threads 0..127, one edge each) ----
    if (tid < 128) {
        int e = e0 + tid;
        int src, dst;
        if (g_idx32) {
            const int* e32 = (const int*)eidx;
            src = e32[e];
            dst = e32[N_EDGES + e];
        } else {
            src = (int)eidx[e];
            dst = (int)eidx[N_EDGES + e];
        }
        src = min(max(src, 0), N_NODES - 1);
        dst = min(max(dst, 0), N_NODES - 1);
        esrc[tid] = src;
        const float* na = node_attr + (size_t)dst * DD;
        float ss = edge_sh[(size_t)e * 4 + 0];
        float v0 = edge_sh[(size_t)e * 4 + 1];
        float v1 = edge_sh[(size_t)e * 4 + 2];
        float v2 = edge_sh[(size_t)e * 4 + 3];
        svs[tid * 3 + 0] = v0; svs[tid * 3 + 1] = v1; svs[tid * 3 + 2] = v2;
        #pragma unroll
        for (int i = 0; i < 32; ++i) {
            float x = na[i];
            xsh[tid * 32 + i] = x;
            sxs[tid * 32 + i] = x * ss;
        }
        #pragma unroll
        for (int i = 0; i < 8; ++i) {
            float a = na[32 + i * 3 + 0];
            float b = na[32 + i * 3 + 1];
            float c = na[32 + i * 3 + 2];
            xvs[tid * 24 + i * 3 + 0] = a * ss;
            xvs[tid * 24 + i * 3 + 1] = b * ss;
            xvs[tid * 24 + i * 3 + 2] = c * ss;
            dvv[tid * 8 + i] = (a * v0 + b * v1 + c * v2) * INV_SQRT3;
        }
    }
    // ---- load h tile into As[e][k] ----
    for (int it = 0; it < 16; ++it) {
        int idx = tid + it * 256;
        int r = idx >> 5, c4 = idx & 31;
        float4 v = *(const float4*)&g_h[(size_t)(e0 + r) * HID + c4 * 4];
        *(float4*)&As[r * 128 + c4 * 4] = v;
    }
    __syncthreads();

    int tx = tid & 15, ty = tid >> 4;
    int ct = tid & 63, eg = tid >> 6;
    int vj = 0, vm = 0;
    if (ct >= 32) { int q = ct - 32; vj = q / 3; vm = q - vj * 3; }

    float tpreg[32];
    #pragma unroll
    for (int i = 0; i < 32; ++i) tpreg[i] = 0.f;

    for (int nt = 0; nt < 13; ++nt) {
        int nb = nt * 128;
        // load W2 tile + b2 slice
        for (int it = 0; it < 16; ++it) {
            int idx = tid + it * 256;
            int r = idx >> 5, c4 = idx & 31;
            int col = nb + c4 * 4;
            float4 w = (col < WN) ? *(const float4*)&W2[(size_t)r * WN + col]
                                  : make_float4(0.f, 0.f, 0.f, 0.f);
            *(float4*)&Bs[r * 128 + c4 * 4] = w;
        }
        if (tid < 128) b2s[tid] = (nb + tid < WN) ? b2[nb + tid] : 0.f;
        __syncthreads();

        // GEMM: C[128e x 128c] = As @ Bs  (f32x2-packed)
        u64 acc[8][4];
        #pragma unroll
        for (int i = 0; i < 8; ++i)
            #pragma unroll
            for (int j = 0; j < 4; ++j) acc[i][j] = 0ull;

        #pragma unroll 2
        for (int k4 = 0; k4 < 32; ++k4) {
            int k0 = k4 * 4;
            float4 av[8];
            #pragma unroll
            for (int mi = 0; mi < 8; ++mi) {
                int m = (mi < 4) ? (ty * 4 + mi) : (64 + ty * 4 + mi - 4);
                av[mi] = *(const float4*)&As[m * 128 + k0];
            }
            #pragma unroll
            for (int kk = 0; kk < 4; ++kk) {
                int k = k0 + kk;
                ulonglong2 bl = *(const ulonglong2*)&Bs[k * 128 + tx * 4];
                ulonglong2 bh = *(const ulonglong2*)&Bs[k * 128 + 64 + tx * 4];
                u64 bb0 = bl.x, bb1 = bl.y, bb2 = bh.x, bb3 = bh.y;
                #pragma unroll
                for (int mi = 0; mi < 8; ++mi) {
                    float a_s = ((const float*)&av[mi])[kk];
                    u64 aa; PACKDUP(aa, a_s);
                    FMA2(acc[mi][0], aa, bb0);
                    FMA2(acc[mi][1], aa, bb1);
                    FMA2(acc[mi][2], aa, bb2);
                    FMA2(acc[mi][3], aa, bb3);
                }
            }
        }
        __syncthreads();  // everyone done reading Bs

        // write C (+b2) into shared, reusing Bs as Cs[e][c]
        float* Cs = Bs;
        #pragma unroll
        for (int mi = 0; mi < 8; ++mi) {
            int m = (mi < 4) ? (ty * 4 + mi) : (64 + ty * 4 + mi - 4);
            #pragma unroll
            for (int p = 0; p < 4; ++p) {
                int n = (p < 2) ? (tx * 4 + p * 2) : (64 + tx * 4 + (p - 2) * 2);
                u64 bias = *(const u64*)&b2s[n];
                u64 r; ADD2(r, acc[mi][p], bias);
                *(u64*)&Cs[m * 128 + n] = r;
            }
        }
        __syncthreads();

        // contraction into tpreg
        if (ct < 32) {
            if (nt < 8) {                 // w_ss: coef = xs*ss, i = nt*4+ii
                #pragma unroll
                for (int e = 0; e < 32; ++e) {
                    int ee = eg * 32 + e;
                    const float* cr = &Cs[ee * 128];
                    const float* co = &sxs[ee * 32 + nt * 4];
                    tpreg[e] += cr[ct] * co[0] + cr[32 + ct] * co[1]
                              + cr[64 + ct] * co[2] + cr[96 + ct] * co[3];
                }
            } else if (nt < 10) {         // w_vs: coef = dot_vv
                #pragma unroll
                for (int e = 0; e < 32; ++e) {
                    int ee = eg * 32 + e;
                    const float* cr = &Cs[ee * 128];
                    const float* co = &dvv[ee * 8 + (nt - 8) * 4];
                    tpreg[e] += cr[ct] * co[0] + cr[32 + ct] * co[1]
                              + cr[64 + ct] * co[2] + cr[96 + ct] * co[3];
                }
            }
        } else if (ct < 56) {
            if (nt >= 10 && nt < 12) {    // w_sv: (sum_i C*xs[i]) * sv[m]
                int ib = (nt - 10) * 16;
                #pragma unroll
                for (int e = 0; e < 32; ++e) {
                    int ee = eg * 32 + e;
                    const float* cr = &Cs[ee * 128 + vj];
                    const float* xr = &xsh[ee * 32 + ib];
                    float a2 = 0.f;
                    #pragma unroll
                    for (int ii = 0; ii < 16; ++ii) a2 += cr[ii * 8] * xr[ii];
                    tpreg[e] += a2 * svs[ee * 3 + vm];
                }
            } else if (nt == 12) {        // w_vv: coef = xv*ss
                #pragma unroll
                for (int e = 0; e < 32; ++e) {
                    int ee = eg * 32 + e;
                    const float* cr = &Cs[ee * 128 + vj];
                    const float* xr = &xvs[ee * 24 + vm];
                    float a2 = 0.f;
                    #pragma unroll
                    for (int ii = 0; ii < 8; ++ii) a2 += cr[ii * 8] * xr[ii * 3];
                    tpreg[e] += a2;
                }
            }
        }
        __syncthreads();
    }

    // scatter to nodes
    if (ct < 56) {
        #pragma unroll
        for (int e = 0; e < 32; ++e) {
            int s = esrc[eg * 32 + e];
            atomicAdd(&g_sums[(size_t)s * DD + ct], tpreg[e] * PATH_NORM);
        }
    } else if (ct == 56) {
        #pragma unroll
        for (int e = 0; e < 32; ++e)
            atomicAdd(&g_cnt[esrc[eg * 32 + e]], 1.0f);
    }
}

// ============================================================
// K4: pre = sums/max(cnt,1) + node_attr ; accumulate BN stats
// ============================================================
__global__ void k4_pre_stats(const float* __restrict__ node_attr) {
    __shared__ float bins[72];
    int tid = threadIdx.x;
    if (tid < 72) bins[tid] = 0.f;
    __syncthreads();
    int idx = blockIdx.x * 256 + tid;     // exactly N_NODES*DD
    int n = idx / DD, f = idx - n * DD;
    float val = g_sums[idx] / fmaxf(g_cnt[n], 1.0f) + node_attr[idx];
    g_pre[idx] = val;
    if (f < NS) {
        atomicAdd(&bins[f], val);
        atomicAdd(&bins[32 + f], val * val);
    } else {
        atomicAdd(&bins[64 + (f - NS) / 3], val * val);
    }
    __syncthreads();
    if (tid < 72) atomicAdd(&g_stats[tid], bins[tid]);
}

// ============================================================
// K5: batch-norm finalize -> d_out
// ============================================================
__global__ void k5_norm(const float* __restrict__ gamma,
                        const float* __restrict__ beta,
                        float* __restrict__ out) {
    int idx = blockIdx.x * 256 + threadIdx.x;
    int n = idx / DD, f = idx - n * DD;
    (void)n;
    float val = g_pre[idx];
    float o;
    if (f < NS) {
        float mean = g_stats[f] * (1.0f / N_NODES);
        float var  = g_stats[32 + f] * (1.0f / N_NODES) - mean * mean;
        o = (val - mean) * rsqrtf(var + EPS) * gamma[f] + beta[f];
    } else {
        int i = (f - NS) / 3;
        float vn2 = g_stats[64 + i] * (1.0f / N_NODES);
        o = val * rsqrtf(vn2 + EPS) * gamma[NS + i];
    }
    out[idx] = o;
}

// ============================================================
extern "C" void kernel_launch(void* const* d_in, const int* in_sizes, int n_in,
                              void* d_out, int out_size) {
    // Bind inputs by UNIQUE element count — robust to metadata ordering.
    const float* node_attr = nullptr;   // 16384*56   = 917504
    const float* edge_attr = nullptr;   // 131072*128 = 16777216
    const float* edge_sh   = nullptr;   // 131072*4   = 524288
    const float* W1 = nullptr;          // 128*128    = 16384
    const float* b1 = nullptr;          // 128
    const float* W2 = nullptr;          // 128*1600   = 204800
    const float* b2 = nullptr;          // 1600
    const float* gamma = nullptr;       // 40
    const float* beta  = nullptr;       // 32
    const long long* eidx = nullptr;    // 2*131072   = 262144

    for (int i = 0; i < n_in; ++i) {
        switch (in_sizes[i]) {
            case 917504:   node_attr = (const float*)d_in[i]; break;
            case 16777216: edge_attr = (const float*)d_in[i]; break;
            case 524288:   edge_sh   = (const float*)d_in[i]; break;
            case 16384:    W1 = (const float*)d_in[i]; break;
            case 128:      b1 = (const float*)d_in[i]; break;
            case 204800:   W2 = (const float*)d_in[i]; break;
            case 1600:     b2 = (const float*)d_in[i]; break;
            case 40:       gamma = (const float*)d_in[i]; break;
            case 32:       beta  = (const float*)d_in[i]; break;
            case 262144:   eidx = (const long long*)d_in[i]; break;
            default: break;
        }
    }
    float* out = (float*)d_out;
    (void)out_size;

    cudaFuncSetAttribute(k1_gemm_relu, cudaFuncAttributeMaxDynamicSharedMemorySize, 131072);
    cudaFuncSetAttribute(k2_fused,     cudaFuncAttributeMaxDynamicSharedMemorySize, 182784);

    k0_zero<<<3584, 256>>>(eidx);
    k1_gemm_relu<<<N_EDGES / 128, 256, 131072>>>(edge_attr, W1, b1);
    k2_fused<<<N_EDGES / 128, 256, 182784>>>(node_attr, edge_sh, W2, b2, eidx);
    k4_pre_stats<<<(N_NODES * DD) / 256, 256>>>(node_attr);
    k5_norm<<<(N_NODES * DD) / 256, 256>>>(gamma, beta, out);
}

// round 12
// speedup vs baseline: 1.3985x; 1.3985x over previous
#include <cuda_runtime.h>
#include <cuda_bf16.h>
#include <cstdint>

#define NS 32
#define NV 8
#define N_NODES 16384
#define N_EDGES 131072
#define NEF 128
#define HID 128
#define WN 1600
#define WNP 1664            /* padded to 13*128 */
#define DD 56
#define INV_SQRT3 0.57735026918962576451f
#define PATH_NORM 0.15811388300841897f /* 1/sqrt(40) */
#define EPS 1e-5f

// ---------------- scratch (static device globals) ----------------
__device__ __nv_bfloat16 g_h_hi[(size_t)N_EDGES * HID];   // 32 MB
__device__ __nv_bfloat16 g_h_lo[(size_t)N_EDGES * HID];   // 32 MB
__device__ __nv_bfloat16 g_W2t_hi[(size_t)WNP * HID];     // [c][k]
__device__ __nv_bfloat16 g_W2t_lo[(size_t)WNP * HID];
__device__ float g_sums[(size_t)N_NODES * DD];
__device__ float g_cnt[N_NODES];
__device__ float g_pre[(size_t)N_NODES * DD];
__device__ float g_stats[72];
__device__ int   g_idx32;

// ---------------- f32x2 helpers (K1 SGEMM) ----------------
#define PACKDUP(dst, s) do { unsigned _u = __float_as_uint(s); \
    asm("mov.b64 %0, {%1, %1};" : "=l"(dst) : "r"(_u)); } while (0)
#define FMA2(d, a, b) asm("fma.rn.f32x2 %0, %1, %2, %0;" : "+l"(d) : "l"(a), "l"(b))
#define UNPACK2(lo, hi, v) do { unsigned _lo, _hi; \
    asm("mov.b64 {%0, %1}, %2;" : "=r"(_lo), "=r"(_hi) : "l"(v)); \
    lo = __uint_as_float(_lo); hi = __uint_as_float(_hi); } while (0)

typedef unsigned long long u64;

__device__ __forceinline__ uint32_t smem_u32(const void* p) {
    uint32_t a;
    asm("{ .reg .u64 t; cvta.to.shared.u64 t, %1; cvt.u32.u64 %0, t; }" : "=r"(a) : "l"(p));
    return a;
}

#define LDSM_X4(r0, r1, r2, r3, addr) \
    asm volatile("ldmatrix.sync.aligned.m8n8.x4.shared.b16 {%0,%1,%2,%3}, [%4];" \
        : "=r"(r0), "=r"(r1), "=r"(r2), "=r"(r3) : "r"(addr))

#define MMA_BF16(c, a0, a1, a2, a3, b0, b1) \
    asm volatile("mma.sync.aligned.m16n8k16.row.col.f32.bf16.bf16.f32 " \
        "{%0,%1,%2,%3}, {%4,%5,%6,%7}, {%8,%9}, {%0,%1,%2,%3};" \
        : "+f"((c)[0]), "+f"((c)[1]), "+f"((c)[2]), "+f"((c)[3]) \
        : "r"(a0), "r"(a1), "r"(a2), "r"(a3), "r"(b0), "r"(b1))

// ---------------- K2 SMEM layout (byte offsets) ----------------
// A/B tiles: 128 rows x 136 bf16 (stride 272 B, 16B-aligned)
#define TSTRIDE 272
#define TILE_B  34816           /* 128*272 */
#define SA_HI 0
#define SA_LO 34816
#define SB_HI 69632
#define SB_LO 104448
#define SCS   69632             /* Cs aliases B region; 128x129 floats = 66048 B */
#define CS_STRIDE 129
#define SB2S  139264
#define SSXS  139776
#define SXSH  156160
#define SDVV  172544
#define SXVS  176640
#define SSVS  188928
#define SESRC 190464
#define K2_SMEM 190976

// ============================================================
// K0: zero accumulators + detect edge_index dtype
// ============================================================
__global__ void k0_zero(const long long* __restrict__ eidx) {
    int idx = blockIdx.x * 256 + threadIdx.x;
    if (idx < N_NODES * DD) g_sums[idx] = 0.f;
    if (idx < N_NODES)      g_cnt[idx]  = 0.f;
    if (idx < 72)           g_stats[idx] = 0.f;
    if (blockIdx.x == 0 && threadIdx.x == 0) {
        int is32 = 0;
        for (int i = 0; i < 64; ++i) {
            long long v = eidx[i];
            if (v < 0 || v >= N_NODES) { is32 = 1; break; }
        }
        g_idx32 = is32;
    }
}

// ============================================================
// K_prep: W2^T -> bf16 hi/lo planes  g_W2t[c][k], zero-padded c>=1600
// ============================================================
__global__ void k_prep(const float* __restrict__ W2) {
    int idx = blockIdx.x * 256 + threadIdx.x;   // WNP*HID total
    if (idx >= WNP * HID) return;
    int c = idx >> 7, k = idx & 127;
    float w = (c < WN) ? W2[(size_t)k * WN + c] : 0.f;
    __nv_bfloat16 hi = __float2bfloat16(w);
    float r = w - __bfloat162float(hi);
    g_W2t_hi[idx] = hi;
    g_W2t_lo[idx] = __float2bfloat16(r);
}

// ============================================================
// K1: h = relu(edge_attr @ W1 + b1) -> bf16 hi/lo planes
// ============================================================
__global__ __launch_bounds__(256, 1)
void k1_gemm_relu(const float* __restrict__ ea, const float* __restrict__ W1,
                  const float* __restrict__ b1) {
    extern __shared__ float sm[];
    float* As = sm;          // 128x128
    float* Bs = sm + 16384;  // 128x128
    int tid = threadIdx.x;
    int e0 = blockIdx.x * 128;

    for (int it = 0; it < 16; ++it) {
        int idx = tid + it * 256;
        int r = idx >> 5, c4 = idx & 31;
        *(float4*)&As[r * 128 + c4 * 4] = *(const float4*)&ea[(size_t)(e0 + r) * NEF + c4 * 4];
        *(float4*)&Bs[r * 128 + c4 * 4] = *(const float4*)&W1[(size_t)r * HID + c4 * 4];
    }
    __syncthreads();

    int tx = tid & 15, ty = tid >> 4;
    u64 acc[8][4];
    #pragma unroll
    for (int i = 0; i < 8; ++i)
        #pragma unroll
        for (int j = 0; j < 4; ++j) acc[i][j] = 0ull;

    #pragma unroll 2
    for (int k4 = 0; k4 < 32; ++k4) {
        int k0 = k4 * 4;
        float4 av[8];
        #pragma unroll
        for (int mi = 0; mi < 8; ++mi) {
            int m = (mi < 4) ? (ty * 4 + mi) : (64 + ty * 4 + mi - 4);
            av[mi] = *(const float4*)&As[m * 128 + k0];
        }
        #pragma unroll
        for (int kk = 0; kk < 4; ++kk) {
            int k = k0 + kk;
            ulonglong2 bl = *(const ulonglong2*)&Bs[k * 128 + tx * 4];
            ulonglong2 bh = *(const ulonglong2*)&Bs[k * 128 + 64 + tx * 4];
            u64 bb0 = bl.x, bb1 = bl.y, bb2 = bh.x, bb3 = bh.y;
            #pragma unroll
            for (int mi = 0; mi < 8; ++mi) {
                float a_s = ((const float*)&av[mi])[kk];
                u64 aa; PACKDUP(aa, a_s);
                FMA2(acc[mi][0], aa, bb0);
                FMA2(acc[mi][1], aa, bb1);
                FMA2(acc[mi][2], aa, bb2);
                FMA2(acc[mi][3], aa, bb3);
            }
        }
    }

    #pragma unroll
    for (int mi = 0; mi < 8; ++mi) {
        int m = (mi < 4) ? (ty * 4 + mi) : (64 + ty * 4 + mi - 4);
        #pragma unroll
        for (int p = 0; p < 4; ++p) {
            int n = (p < 2) ? (tx * 4 + p * 2) : (64 + tx * 4 + (p - 2) * 2);
            float c0, c1; UNPACK2(c0, c1, acc[mi][p]);
            c0 = fmaxf(c0 + __ldg(&b1[n]), 0.f);
            c1 = fmaxf(c1 + __ldg(&b1[n + 1]), 0.f);
            __nv_bfloat16 h0 = __float2bfloat16(c0);
            __nv_bfloat16 h1 = __float2bfloat16(c1);
            __nv_bfloat16 l0 = __float2bfloat16(c0 - __bfloat162float(h0));
            __nv_bfloat16 l1 = __float2bfloat16(c1 - __bfloat162float(h1));
            size_t off = (size_t)(e0 + m) * HID + n;
            *(__nv_bfloat162*)&g_h_hi[off] = __nv_bfloat162(h0, h1);
            *(__nv_bfloat162*)&g_h_lo[off] = __nv_bfloat162(l0, l1);
        }
    }
}

// ============================================================
// K2: mma.sync split-bf16 GEMM (w = h@W2 + b2) -> tensor product -> scatter
// 8 warps: warp tile 32(edges) x 64(cols). 3 passes x 8 ksteps x 16 HMMA.
// ============================================================
__global__ __launch_bounds__(256, 1)
void k2_fused(const float* __restrict__ node_attr,
              const float* __restrict__ edge_sh,
              const float* __restrict__ b2,
              const long long* __restrict__ eidx) {
    extern __shared__ char smc[];
    uint32_t sb = smem_u32(smc);

    float* b2s = (float*)(smc + SB2S);
    float* sxs = (float*)(smc + SSXS);
    float* xsh = (float*)(smc + SXSH);
    float* dvv = (float*)(smc + SDVV);
    float* xvs = (float*)(smc + SXVS);
    float* svs = (float*)(smc + SSVS);
    int*  esrc = (int*)(smc + SESRC);
    float* Cs  = (float*)(smc + SCS);

    int tid = threadIdx.x;
    int wid = tid >> 5, lid = tid & 31;
    int e0 = blockIdx.x * 128;

    // ---- per-edge prep ----
    if (tid < 128) {
        int e = e0 + tid;
        int src, dst;
        if (g_idx32) {
            const int* e32 = (const int*)eidx;
            src = e32[e]; dst = e32[N_EDGES + e];
        } else {
            src = (int)eidx[e]; dst = (int)eidx[N_EDGES + e];
        }
        src = min(max(src, 0), N_NODES - 1);
        dst = min(max(dst, 0), N_NODES - 1);
        esrc[tid] = src;
        const float* na = node_attr + (size_t)dst * DD;
        float ss = edge_sh[(size_t)e * 4 + 0];
        float v0 = edge_sh[(size_t)e * 4 + 1];
        float v1 = edge_sh[(size_t)e * 4 + 2];
        float v2 = edge_sh[(size_t)e * 4 + 3];
        svs[tid * 3 + 0] = v0; svs[tid * 3 + 1] = v1; svs[tid * 3 + 2] = v2;
        #pragma unroll
        for (int i = 0; i < 32; ++i) {
            float x = na[i];
            xsh[tid * 32 + i] = x;
            sxs[tid * 32 + i] = x * ss;
        }
        #pragma unroll
        for (int i = 0; i < 8; ++i) {
            float a = na[32 + i * 3 + 0];
            float b = na[32 + i * 3 + 1];
            float c = na[32 + i * 3 + 2];
            xvs[tid * 24 + i * 3 + 0] = a * ss;
            xvs[tid * 24 + i * 3 + 1] = b * ss;
            xvs[tid * 24 + i * 3 + 2] = c * ss;
            dvv[tid * 8 + i] = (a * v0 + b * v1 + c * v2) * INV_SQRT3;
        }
    }

    // ---- load A tile (h hi/lo) once: [r][k], stride 272 B ----
    {
        const uint4* shi = (const uint4*)g_h_hi + (size_t)e0 * 16;  // 16 uint4/row
        const uint4* slo = (const uint4*)g_h_lo + (size_t)e0 * 16;
        for (int idx = tid; idx < 2048; idx += 256) {
            int r = idx >> 4, c8 = idx & 15;
            int so = r * TSTRIDE + c8 * 16;
            *(uint4*)(smc + SA_HI + so) = shi[r * 16 + c8];
            *(uint4*)(smc + SA_LO + so) = slo[r * 16 + c8];
        }
    }

    int ct = tid & 63, eg = tid >> 6;
    int vj = 0, vm = 0;
    if (ct >= 32) { int q = ct - 32; vj = q / 3; vm = q - vj * 3; }

    float tpreg[32];
    #pragma unroll
    for (int i = 0; i < 32; ++i) tpreg[i] = 0.f;

    // warp tile: rows mrow..mrow+31, cols ncol..ncol+63
    int mrow = (wid & 3) * 32;
    int ncol = (wid >> 2) * 64;
    int g = lid >> 2, t = lid & 3;

    // LDSM lane addressing (within warp tile)
    int a_row = lid & 15;                      // lanes 0-15 / 16-31 same rows
    int a_koff = (lid & 16) ? 16 : 0;          // +8 cols * 2B
    int b_n = (lid & 7) + ((lid & 16) ? 8 : 0);
    int b_koff = (lid & 8) ? 16 : 0;

    for (int nt = 0; nt < 13; ++nt) {
        int nb = nt * 128;
        __syncthreads();   // prev contraction done -> B/Cs region free

        // ---- load B tile (W2t rows nb..nb+127) hi/lo ----
        {
            const uint4* bhi = (const uint4*)g_W2t_hi + (size_t)nb * 16;
            const uint4* blo = (const uint4*)g_W2t_lo + (size_t)nb * 16;
            for (int idx = tid; idx < 2048; idx += 256) {
                int r = idx >> 4, c8 = idx & 15;
                int so = r * TSTRIDE + c8 * 16;
                *(uint4*)(smc + SB_HI + so) = bhi[r * 16 + c8];
                *(uint4*)(smc + SB_LO + so) = blo[r * 16 + c8];
            }
        }
        if (tid < 128) b2s[tid] = (nb + tid < WN) ? b2[nb + tid] : 0.f;
        __syncthreads();

        // ---- GEMM: acc[2][8][4] over 3 split passes ----
        float acc[2][8][4];
        #pragma unroll
        for (int mt = 0; mt < 2; ++mt)
            #pragma unroll
            for (int j = 0; j < 8; ++j)
                #pragma unroll
                for (int q = 0; q < 4; ++q) acc[mt][j][q] = 0.f;

        const int pA[3] = {SA_HI, SA_HI, SA_LO};
        const int pB[3] = {SB_HI, SB_LO, SB_HI};
        #pragma unroll
        for (int p = 0; p < 3; ++p) {
            uint32_t aBase = sb + pA[p] + (mrow + a_row) * TSTRIDE + a_koff;
            uint32_t bBase = sb + pB[p] + (ncol + b_n) * TSTRIDE + b_koff;  // FIX: + ncol
            #pragma unroll
            for (int ks = 0; ks < 8; ++ks) {
                int k2b = ks * 32;   // 16 bf16 = 32 B per kstep
                uint32_t af[2][4];
                LDSM_X4(af[0][0], af[0][1], af[0][2], af[0][3], aBase + k2b);
                LDSM_X4(af[1][0], af[1][1], af[1][2], af[1][3], aBase + 16 * TSTRIDE + k2b);
                uint32_t bf[8][2];
                #pragma unroll
                for (int j2 = 0; j2 < 4; ++j2) {
                    uint32_t r0, r1, r2, r3;
                    LDSM_X4(r0, r1, r2, r3, bBase + j2 * 16 * TSTRIDE + k2b);
                    bf[j2 * 2][0] = r0; bf[j2 * 2][1] = r1;
                    bf[j2 * 2 + 1][0] = r2; bf[j2 * 2 + 1][1] = r3;
                }
                #pragma unroll
                for (int mt = 0; mt < 2; ++mt)
                    #pragma unroll
                    for (int j = 0; j < 8; ++j)
                        MMA_BF16(acc[mt][j], af[mt][0], af[mt][1], af[mt][2], af[mt][3],
                                 bf[j][0], bf[j][1]);
            }
        }
        __syncthreads();  // all warps done reading Bs

        // ---- epilogue: acc + b2 -> Cs ----
        #pragma unroll
        for (int mt = 0; mt < 2; ++mt) {
            int r0 = mrow + mt * 16 + g;
            #pragma unroll
            for (int j = 0; j < 8; ++j) {
                int c = ncol + j * 8 + 2 * t;
                Cs[r0 * CS_STRIDE + c]           = acc[mt][j][0] + b2s[c];
                Cs[r0 * CS_STRIDE + c + 1]       = acc[mt][j][1] + b2s[c + 1];
                Cs[(r0 + 8) * CS_STRIDE + c]     = acc[mt][j][2] + b2s[c];
                Cs[(r0 + 8) * CS_STRIDE + c + 1] = acc[mt][j][3] + b2s[c + 1];
            }
        }
        __syncthreads();

        // ---- contraction into tpreg ----
        if (ct < 32) {
            if (nt < 8) {                 // w_ss
                #pragma unroll
                for (int e = 0; e < 32; ++e) {
                    int ee = eg * 32 + e;
                    const float* cr = &Cs[ee * CS_STRIDE];
                    const float* co = &sxs[ee * 32 + nt * 4];
                    tpreg[e] += cr[ct] * co[0] + cr[32 + ct] * co[1]
                              + cr[64 + ct] * co[2] + cr[96 + ct] * co[3];
                }
            } else if (nt < 10) {         // w_vs
                #pragma unroll
                for (int e = 0; e < 32; ++e) {
                    int ee = eg * 32 + e;
                    const float* cr = &Cs[ee * CS_STRIDE];
                    const float* co = &dvv[ee * 8 + (nt - 8) * 4];
                    tpreg[e] += cr[ct] * co[0] + cr[32 + ct] * co[1]
                              + cr[64 + ct] * co[2] + cr[96 + ct] * co[3];
                }
            }
        } else if (ct < 56) {
            if (nt >= 10 && nt < 12) {    // w_sv
                int ib = (nt - 10) * 16;
                #pragma unroll
                for (int e = 0; e < 32; ++e) {
                    int ee = eg * 32 + e;
                    const float* cr = &Cs[ee * CS_STRIDE + vj];
                    const float* xr = &xsh[ee * 32 + ib];
                    float a2 = 0.f;
                    #pragma unroll
                    for (int ii = 0; ii < 16; ++ii) a2 += cr[ii * 8] * xr[ii];
                    tpreg[e] += a2 * svs[ee * 3 + vm];
                }
            } else if (nt == 12) {        // w_vv
                #pragma unroll
                for (int e = 0; e < 32; ++e) {
                    int ee = eg * 32 + e;
                    const float* cr = &Cs[ee * CS_STRIDE + vj];
                    const float* xr = &xvs[ee * 24 + vm];
                    float a2 = 0.f;
                    #pragma unroll
                    for (int ii = 0; ii < 8; ++ii) a2 += cr[ii * 8] * xr[ii * 3];
                    tpreg[e] += a2;
                }
            }
        }
    }

    // ---- scatter ----
    if (ct < 56) {
        #pragma unroll
        for (int e = 0; e < 32; ++e) {
            int s = esrc[eg * 32 + e];
            atomicAdd(&g_sums[(size_t)s * DD + ct], tpreg[e] * PATH_NORM);
        }
    } else if (ct == 56) {
        #pragma unroll
        for (int e = 0; e < 32; ++e)
            atomicAdd(&g_cnt[esrc[eg * 32 + e]], 1.0f);
    }
}

// ============================================================
// K4: pre = sums/max(cnt,1) + node_attr ; BN stats
// ============================================================
__global__ void k4_pre_stats(const float* __restrict__ node_attr) {
    __shared__ float bins[72];
    int tid = threadIdx.x;
    if (tid < 72) bins[tid] = 0.f;
    __syncthreads();
    int idx = blockIdx.x * 256 + tid;
    int n = idx / DD, f = idx - n * DD;
    float val = g_sums[idx] / fmaxf(g_cnt[n], 1.0f) + node_attr[idx];
    g_pre[idx] = val;
    if (f < NS) {
        atomicAdd(&bins[f], val);
        atomicAdd(&bins[32 + f], val * val);
    } else {
        atomicAdd(&bins[64 + (f - NS) / 3], val * val);
    }
    __syncthreads();
    if (tid < 72) atomicAdd(&g_stats[tid], bins[tid]);
}

// ============================================================
// K5: batch-norm finalize -> out
// ============================================================
__global__ void k5_norm(const float* __restrict__ gamma,
                        const float* __restrict__ beta,
                        float* __restrict__ out) {
    int idx = blockIdx.x * 256 + threadIdx.x;
    int f = idx % DD;
    float val = g_pre[idx];
    float o;
    if (f < NS) {
        float mean = g_stats[f] * (1.0f / N_NODES);
        float var  = g_stats[32 + f] * (1.0f / N_NODES) - mean * mean;
        o = (val - mean) * rsqrtf(var + EPS) * gamma[f] + beta[f];
    } else {
        int i = (f - NS) / 3;
        float vn2 = g_stats[64 + i] * (1.0f / N_NODES);
        o = val * rsqrtf(vn2 + EPS) * gamma[NS + i];
    }
    out[idx] = o;
}

// ============================================================
extern "C" void kernel_launch(void* const* d_in, const int* in_sizes, int n_in,
                              void* d_out, int out_size) {
    const float* node_attr = nullptr;
    const float* edge_attr = nullptr;
    const float* edge_sh   = nullptr;
    const float* W1 = nullptr;
    const float* b1 = nullptr;
    const float* W2 = nullptr;
    const float* b2 = nullptr;
    const float* gamma = nullptr;
    const float* beta  = nullptr;
    const long long* eidx = nullptr;

    for (int i = 0; i < n_in; ++i) {
        switch (in_sizes[i]) {
            case 917504:   node_attr = (const float*)d_in[i]; break;
            case 16777216: edge_attr = (const float*)d_in[i]; break;
            case 524288:   edge_sh   = (const float*)d_in[i]; break;
            case 16384:    W1 = (const float*)d_in[i]; break;
            case 128:      b1 = (const float*)d_in[i]; break;
            case 204800:   W2 = (const float*)d_in[i]; break;
            case 1600:     b2 = (const float*)d_in[i]; break;
            case 40:       gamma = (const float*)d_in[i]; break;
            case 32:       beta  = (const float*)d_in[i]; break;
            case 262144:   eidx = (const long long*)d_in[i]; break;
            default: break;
        }
    }
    float* out = (float*)d_out;
    (void)out_size;

    cudaFuncSetAttribute(k1_gemm_relu, cudaFuncAttributeMaxDynamicSharedMemorySize, 131072);
    cudaFuncSetAttribute(k2_fused,     cudaFuncAttributeMaxDynamicSharedMemorySize, K2_SMEM);

    k0_zero<<<3584, 256>>>(eidx);
    k_prep<<<(WNP * HID + 255) / 256, 256>>>(W2);
    k1_gemm_relu<<<N_EDGES / 128, 256, 131072>>>(edge_attr, W1, b1);
    k2_fused<<<N_EDGES / 128, 256, K2_SMEM>>>(node_attr, edge_sh, b2, eidx);
    k4_pre_stats<<<(N_NODES * DD) / 256, 256>>>(node_attr);
    k5_norm<<<(N_NODES * DD) / 256, 256>>>(gamma, beta, out);
}